// round 1
// baseline (speedup 1.0000x reference)
#include <cuda_runtime.h>

#define FULLMASK 0xffffffffu
constexpr int Bn = 2048;
constexpr int Sn = 2048;
constexpr int Hn = 64;

__device__ __forceinline__ unsigned long long pack2(float lo, float hi) {
    unsigned long long r;
    asm("mov.b64 %0, {%1, %2};" : "=l"(r) : "f"(lo), "f"(hi));
    return r;
}
__device__ __forceinline__ float2 unpack2(unsigned long long v) {
    float2 r;
    asm("mov.b64 {%0, %1}, %2;" : "=f"(r.x), "=f"(r.y) : "l"(v));
    return r;
}
// packed dual-FMA: d.lo += a.lo*b.lo ; d.hi += a.hi*b.hi
__device__ __forceinline__ void ffma2(unsigned long long& d, unsigned long long a, unsigned long long b) {
    asm("fma.rn.f32x2 %0, %1, %2, %0;" : "+l"(d) : "l"(a), "l"(b));
}

__global__ void __launch_bounds__(64, 7) rnn_garch_kernel(
    const float* __restrict__ res,   // (B, S)
    const float* __restrict__ Wih,   // (H, 2)
    const float* __restrict__ Bih,   // (H,)
    const float* __restrict__ Whh,   // (H, H)
    const float* __restrict__ Bhh,   // (H,)
    const float* __restrict__ Fcw,   // (1, H)
    const float* __restrict__ Fcb,   // (1,)
    float* __restrict__ out)         // (B, S)
{
    __shared__ __align__(16) float hsm[2][2][Hn];   // [warp][buf][H]
    __shared__ float4 c0s[2][32];                   // wih per lane
    __shared__ float4 c1s[2][32];                   // biases + fc per lane

    const int lane = threadIdx.x & 31;
    const int wib  = threadIdx.x >> 5;
    const int b    = (blockIdx.x << 1) | wib;

    const float* rrow = res + (size_t)b * Sn;
    float*       orow = out + (size_t)b * Sn;

    const int r0 = lane * 2;
    const int r1 = r0 + 1;

    // ---- one-time setup: W_hh rows r0,r1 packed as f32x2 pairs along j ----
    unsigned long long w0[32], w1[32];
    {
        const float2* W2 = reinterpret_cast<const float2*>(Whh);
        #pragma unroll
        for (int k = 0; k < 32; ++k) {
            float2 a = W2[r0 * 32 + k];
            float2 c = W2[r1 * 32 + k];
            w0[k] = pack2(a.x, a.y);
            w1[k] = pack2(c.x, c.y);
        }
        float2 wa = reinterpret_cast<const float2*>(Wih)[r0];
        float2 wb = reinterpret_cast<const float2*>(Wih)[r1];
        c0s[wib][lane] = make_float4(wa.x, wa.y, wb.x, wb.y);
        c1s[wib][lane] = make_float4(Bih[r0] + Bhh[r0], Bih[r1] + Bhh[r1],
                                     Fcw[r0], Fcw[r1]);
    }
    const float fcb0 = Fcb[0];

    // ---- sigma0 = unbiased variance of the residual row ----
    float sum = 0.f, sq = 0.f;
    #pragma unroll 4
    for (int k = lane; k < Sn; k += 32) {
        float x = rrow[k];
        sum += x;
        sq = fmaf(x, x, sq);
    }
    #pragma unroll
    for (int o = 16; o; o >>= 1) {
        sum += __shfl_xor_sync(FULLMASK, sum, o);
        sq  += __shfl_xor_sync(FULLMASK, sq, o);
    }
    float sigma = (sq - sum * sum * (1.f / Sn)) * (1.f / (Sn - 1));
    if (lane == 0) orow[0] = sigma;

    // ---- init h buffer 0 to zero (h0 = 0) ----
    reinterpret_cast<float2*>(hsm[wib][0])[lane] = make_float2(0.f, 0.f);
    __syncwarp();

    const ulonglong2* hr0 = reinterpret_cast<const ulonglong2*>(hsm[wib][0]);
    const ulonglong2* hr1 = reinterpret_cast<const ulonglong2*>(hsm[wib][1]);
    float2* hw0 = reinterpret_cast<float2*>(hsm[wib][0]);
    float2* hw1 = reinterpret_cast<float2*>(hsm[wib][1]);

    auto step = [&](int t, const ulonglong2* hr, float2* hw) {
        float eps = __ldg(rrow + (t - 1));   // broadcast load, L1-resident

        // matvec: rows r0,r1 of W_hh times h, packed pairs over j
        unsigned long long a = 0ull, c = 0ull;
        #pragma unroll
        for (int k = 0; k < 16; ++k) {
            ulonglong2 hh = hr[k];           // LDS.128 broadcast: h[4k..4k+3]
            ffma2(a, w0[2 * k],     hh.x);
            ffma2(c, w1[2 * k],     hh.x);
            ffma2(a, w0[2 * k + 1], hh.y);
            ffma2(c, w1[2 * k + 1], hh.y);
        }

        float4 cw = c0s[wib][lane];
        float4 cb = c1s[wib][lane];
        float e2 = eps * eps;
        float baseA = fmaf(e2, cw.x, fmaf(sigma, cw.y, cb.x));
        float baseB = fmaf(e2, cw.z, fmaf(sigma, cw.w, cb.y));
        float2 ua = unpack2(a), uc = unpack2(c);
        float hA = baseA + (ua.x + ua.y);
        float hB = baseB + (uc.x + uc.y);
        hw[lane] = make_float2(hA, hB);      // write next h buffer

        // fc dot + softplus
        float pd = fmaf(hA, cb.z, hB * cb.w);
        #pragma unroll
        for (int o = 16; o; o >>= 1) pd += __shfl_xor_sync(FULLMASK, pd, o);
        float x = pd + fcb0;
        float sp = (x > 15.f) ? x : log1pf(__expf(x));
        sigma = sp + 1e-6f;

        if ((t < Sn) && (lane == (t & 31))) orow[t] = sigma;
        __syncwarp();
    };

    #pragma unroll 1
    for (int t = 1; t < Sn; t += 2) {
        step(t,     hr0, hw1);
        step(t + 1, hr1, hw0);   // t+1==Sn on last iter: compute runs, store is guarded off
    }
}

extern "C" void kernel_launch(void* const* d_in, const int* in_sizes, int n_in,
                              void* d_out, int out_size) {
    (void)in_sizes; (void)n_in; (void)out_size;
    rnn_garch_kernel<<<Bn / 2, 64>>>(
        (const float*)d_in[0],  // residuals
        (const float*)d_in[1],  // W_ih_w
        (const float*)d_in[2],  // W_ih_b
        (const float*)d_in[3],  // W_hh_w
        (const float*)d_in[4],  // W_hh_b
        (const float*)d_in[5],  // fc_w
        (const float*)d_in[6],  // fc_b
        (float*)d_out);
}